// round 10
// baseline (speedup 1.0000x reference)
#include <cuda_runtime.h>
#include <math_constants.h>

// EnhancedLIFNeuron: B=128, T=128, F=2048, KW=5
// inputs: x[B*T*F] f32, init_threshold[1], conv_w[5], conv_b[1], spatial_attn[1]
// output: spikes[B,T,F] then mem[B,F], f32.

#define TT     128
#define FF     2048
#define FQ     (FF/4)      // ulonglong2 (16B) stride per timestep = 512
#define BB     128
#define BLOCK  128

typedef unsigned long long ull;

// ---- packed f32x2 helpers ----
__device__ __forceinline__ ull pk2(float l, float h) {
    ull r; asm("mov.b64 %0, {%1, %2};" : "=l"(r) : "f"(l), "f"(h)); return r;
}
__device__ __forceinline__ void up2(float& l, float& h, ull v) {
    asm("mov.b64 {%0, %1}, %2;" : "=f"(l), "=f"(h) : "l"(v));
}
__device__ __forceinline__ ull fma2(ull a, ull b, ull c) {
    ull d; asm("fma.rn.f32x2 %0, %1, %2, %3;" : "=l"(d) : "l"(a), "l"(b), "l"(c)); return d;
}
__device__ __forceinline__ ull mul2(ull a, ull b) {
    ull d; asm("mul.rn.f32x2 %0, %1, %2;" : "=l"(d) : "l"(a), "l"(b)); return d;
}
__device__ __forceinline__ ull add2(ull a, ull b) {
    ull d; asm("add.rn.f32x2 %0, %1, %2;" : "=l"(d) : "l"(a), "l"(b)); return d;
}
__device__ __forceinline__ ull sub2(ull a, ull b) {
    ull d; asm("sub.rn.f32x2 %0, %1, %2;" : "=l"(d) : "l"(a), "l"(b)); return d;
}

// atan surrogate: spike = atan((mem-thr)*pi/2)/(2*pi) + 0.25, packed 2 lanes.
// degree-9 odd minimax (|err| ~1e-5 rad) with reciprocal range reduction.
__device__ __forceinline__ ull atan_spike(ull dd)
{
    const ull A1 = pk2( 0.9998660f,  0.9998660f);
    const ull A3 = pk2(-0.3302995f, -0.3302995f);
    const ull A5 = pk2( 0.1801410f,  0.1801410f);
    const ull A7 = pk2(-0.0851330f, -0.0851330f);
    const ull A9 = pk2( 0.0208351f,  0.0208351f);

    float dl, dh; up2(dl, dh, dd);
    float al = fabsf(dl) * 1.5707964f;
    float ah = fabsf(dh) * 1.5707964f;
    float rl = __fdividef(1.0f, al);
    float rh = __fdividef(1.0f, ah);
    ull tk  = pk2(fminf(al, rl), fminf(ah, rh));
    ull tt2 = mul2(tk, tk);
    ull tt4 = mul2(tt2, tt2);
    ull e0  = fma2(tt2, A3, A1);
    ull e1  = fma2(tt2, A7, A5);
    e1 = fma2(tt4, A9, e1);
    ull pp = fma2(tt4, e1, e0);
    ull rr = mul2(tk, pp);
    float prl, prh; up2(prl, prh, rr);
    float aal = (al > 1.0f) ? (1.5707964f - prl) : prl;
    float aah = (ah > 1.0f) ? (1.5707964f - prh) : prh;
    aal = copysignf(aal, dl);
    aah = copysignf(aah, dh);
    return pk2(fmaf(aal, 0.15915494f, 0.25f),
               fmaf(aah, 0.15915494f, 0.25f));
}

__global__ __launch_bounds__(BLOCK, 5)
void lif_fused_kernel(const float* __restrict__ x,
                      const float* __restrict__ thr_p,
                      const float* __restrict__ cw,
                      const float* __restrict__ cb,
                      const float* __restrict__ sa,
                      float* __restrict__ out)
{
    const int p  = blockIdx.x * BLOCK + threadIdx.x;   // quad-lane id in [0, B*FQ)
    const int fp = p & (FQ - 1);
    const int b  = p >> 9;                             // FQ = 2^9
    const int f  = fp * 4;

    const ulonglong2* __restrict__ xq =
        (const ulonglong2*)(x + (size_t)b * TT * FF + f);
    ulonglong2* __restrict__ oq =
        (ulonglong2*)(out + (size_t)b * TT * FF + f);

    const float w0 = cw[0], w1 = cw[1], w2 = cw[2], w3 = cw[3], w4 = cw[4];
    const float bias = cb[0];
    const float thr0 = thr_p[0];
    const float satt = sa[0];

    // ---------- pass 1: sum x over t (packed adds; default caching -> L2) ----------
    ull sA0 = 0ull, sA1 = 0ull, sB0 = 0ull, sB1 = 0ull;
    #pragma unroll 4
    for (int t = 0; t < TT; t += 2) {
        ulonglong2 u = xq[t * FQ];
        ulonglong2 v = xq[(t + 1) * FQ];
        sA0 = add2(sA0, u.x); sB0 = add2(sB0, u.y);
        sA1 = add2(sA1, v.x); sB1 = add2(sB1, v.y);
    }
    const ull sAp = add2(sA0, sA1);
    const ull sBp = add2(sB0, sB1);

    const ulonglong2 xe0 = xq[0];
    const ulonglong2 xe1 = xq[FQ];
    const ulonglong2 xT2 = xq[(TT - 2) * FQ];
    const ulonglong2 xT1 = xq[(TT - 1) * FQ];

    const float wsum = w0 + w1 + w2 + w3 + w4;
    const float cT = (float)TT * bias;

    // per-lane scale = 1 + 0.5*sigmoid(satt*mean_conv)
    float S[4], E0[4], E1[4], T2[4], T1[4], sc[4];
    up2(S[0], S[1], sAp);  up2(S[2], S[3], sBp);
    up2(E0[0], E0[1], xe0.x); up2(E0[2], E0[3], xe0.y);
    up2(E1[0], E1[1], xe1.x); up2(E1[2], E1[3], xe1.y);
    up2(T2[0], T2[1], xT2.x); up2(T2[2], T2[3], xT2.y);
    up2(T1[0], T1[1], xT1.x); up2(T1[2], T1[3], xT1.y);
    #pragma unroll
    for (int i = 0; i < 4; ++i) {
        float scv = cT + wsum * S[i] - w0 * (T2[i] + T1[i]) - w1 * T1[i]
                  - w3 * E0[i] - w4 * (E0[i] + E1[i]);
        sc[i] = 1.0f + 0.5f / (1.0f + expf(-satt * scv * (1.0f / (float)TT)));
    }

    // ---------- packed constants ----------
    const ull W0 = pk2(w0, w0), W1 = pk2(w1, w1), W2 = pk2(w2, w2);
    const ull W3 = pk2(w3, w3), W4 = pk2(w4, w4);
    const ull SCA = pk2(sc[0], sc[1]),  SCB = pk2(sc[2], sc[3]);
    const ull BpA = pk2(bias * sc[0], bias * sc[1]);
    const ull BpB = pk2(bias * sc[2], bias * sc[3]);
    const ull DEC = pk2(0.9f, 0.9f);
    const float k3f = 0.1f / 3.0f;
    const ull K3   = pk2(k3f, k3f);
    const ull TH0C = pk2(0.1f * thr0, 0.1f * thr0);

    // ---------- pass 2: two independent packed LIF chains ----------
    ull m2A = 0ull, m1A = 0ull, c0A = xe0.x, p1A = xe1.x;
    ull m2B = 0ull, m1B = 0ull, c0B = xe0.y, p1B = xe1.y;
    ulonglong2 q2 = xq[2 * FQ];
    ulonglong2 q3 = xq[3 * FQ];
    ull curA0 = q2.x, curB0 = q2.y;
    ull curA1 = q3.x, curB1 = q3.y;

    ull memA = 0ull, memB = 0ull;
    ull thrA = pk2(thr0, thr0), thrB = thrA;
    ull h1A = 0ull, h2A = 0ull, h1B = 0ull, h2B = 0ull;

    #define LIF_STEP(T_, PAR_, PF_)                                             \
    {                                                                            \
        ull p2A = (PAR_) ? curA1 : curA0;                                        \
        ull p2B = (PAR_) ? curB1 : curB0;                                        \
        if (PF_) {                                                               \
            ulonglong2 nv = __ldcs(&xq[((T_) + 4) * FQ]);                        \
            if (PAR_) { curA1 = nv.x; curB1 = nv.y; }                            \
            else      { curA0 = nv.x; curB0 = nv.y; }                            \
        }                                                                        \
        ull cvA = mul2(W0, m2A);                                                 \
        cvA = fma2(W1, m1A, cvA);                                                \
        cvA = fma2(W2, c0A, cvA);                                                \
        cvA = fma2(W3, p1A, cvA);                                                \
        cvA = fma2(W4, p2A, cvA);                                                \
        ull cvB = mul2(W0, m2B);                                                 \
        cvB = fma2(W1, m1B, cvB);                                                \
        cvB = fma2(W2, c0B, cvB);                                                \
        cvB = fma2(W3, p1B, cvB);                                                \
        cvB = fma2(W4, p2B, cvB);                                                \
        memA = fma2(DEC, memA, fma2(cvA, SCA, BpA));                             \
        memB = fma2(DEC, memB, fma2(cvB, SCB, BpB));                             \
        /* thr pre-term computes in parallel with the atan chain */              \
        ull preA = fma2(DEC, thrA, fma2(K3, add2(h1A, h2A), TH0C));              \
        ull preB = fma2(DEC, thrB, fma2(K3, add2(h1B, h2B), TH0C));              \
        ull spA = atan_spike(sub2(memA, thrA));                                  \
        ull spB = atan_spike(sub2(memB, thrB));                                  \
        thrA = fma2(K3, spA, preA);                                              \
        thrB = fma2(K3, spB, preB);                                              \
        memA = sub2(memA, mul2(spA, thrA));                                      \
        memB = sub2(memB, mul2(spB, thrB));                                      \
        h1A = h2A; h2A = spA;                                                    \
        h1B = h2B; h2B = spB;                                                    \
        ulonglong2 stv; stv.x = spA; stv.y = spB;                                \
        __stcs(&oq[(T_) * FQ], stv);                                             \
        m2A = m1A; m1A = c0A; c0A = p1A; p1A = p2A;                              \
        m2B = m1B; m1B = c0B; c0B = p1B; p1B = p2B;                              \
    }

    // main chunks: t = 0..123, prefetch t+4 valid (<= 127)
    #pragma unroll 1
    for (int c = 0; c < 31; ++c) {
        const int tb = c * 4;
        LIF_STEP(tb + 0, 0, true)
        LIF_STEP(tb + 1, 1, true)
        LIF_STEP(tb + 2, 0, true)
        LIF_STEP(tb + 3, 1, true)
    }
    // tail: cur{A,B}0 = x[126], cur{A,B}1 = x[127], consumed at t=124,125.
    LIF_STEP(124, 0, false)
    LIF_STEP(125, 1, false)
    // t=126,127 need x[128],x[129] = 0 (SAME zero padding)
    curA0 = curB0 = 0ull;
    curA1 = curB1 = 0ull;
    LIF_STEP(126, 0, false)
    LIF_STEP(127, 1, false)

    #undef LIF_STEP

    // mem output appended after spikes
    ulonglong2 mv; mv.x = memA; mv.y = memB;
    ((ulonglong2*)(out + (size_t)BB * TT * FF))[p] = mv;
}

extern "C" void kernel_launch(void* const* d_in, const int* in_sizes, int n_in,
                              void* d_out, int out_size)
{
    const float* x    = (const float*)d_in[0];
    const float* thr0 = (const float*)d_in[1];
    const float* cw   = (const float*)d_in[2];
    const float* cb   = (const float*)d_in[3];
    const float* sa   = (const float*)d_in[4];
    float* out = (float*)d_out;

    const int quads = BB * FQ;                 // 65536 threads
    lif_fused_kernel<<<quads / BLOCK, BLOCK>>>(x, thr0, cw, cb, sa, out);
}

// round 11
// speedup vs baseline: 1.1350x; 1.1350x over previous
#include <cuda_runtime.h>
#include <math_constants.h>

// EnhancedLIFNeuron: B=128, T=128, F=2048, KW=5
// inputs: x[B*T*F] f32, init_threshold[1], conv_w[5], conv_b[1], spatial_attn[1]
// output: spikes[B,T,F] then mem[B,F], f32.

#define TT     128
#define FF     2048
#define FH     (FF/2)      // ull (8B, 2 floats) stride per timestep = 1024
#define BB     128
#define BLOCK  128

typedef unsigned long long ull;

// ---- packed f32x2 helpers ----
__device__ __forceinline__ ull pk2(float l, float h) {
    ull r; asm("mov.b64 %0, {%1, %2};" : "=l"(r) : "f"(l), "f"(h)); return r;
}
__device__ __forceinline__ void up2(float& l, float& h, ull v) {
    asm("mov.b64 {%0, %1}, %2;" : "=f"(l), "=f"(h) : "l"(v));
}
__device__ __forceinline__ ull fma2(ull a, ull b, ull c) {
    ull d; asm("fma.rn.f32x2 %0, %1, %2, %3;" : "=l"(d) : "l"(a), "l"(b), "l"(c)); return d;
}
__device__ __forceinline__ ull mul2(ull a, ull b) {
    ull d; asm("mul.rn.f32x2 %0, %1, %2;" : "=l"(d) : "l"(a), "l"(b)); return d;
}
__device__ __forceinline__ ull add2(ull a, ull b) {
    ull d; asm("add.rn.f32x2 %0, %1, %2;" : "=l"(d) : "l"(a), "l"(b)); return d;
}
__device__ __forceinline__ ull sub2(ull a, ull b) {
    ull d; asm("sub.rn.f32x2 %0, %1, %2;" : "=l"(d) : "l"(a), "l"(b)); return d;
}

// spike = atan((mem-thr)*pi/2)/(2*pi) + 0.25, packed 2 lanes.
// degree-9 odd minimax (|err| ~1e-5 rad) + reciprocal range reduction.
__device__ __forceinline__ ull atan_spike(ull dd)
{
    const ull A1 = pk2( 0.9998660f,  0.9998660f);
    const ull A3 = pk2(-0.3302995f, -0.3302995f);
    const ull A5 = pk2( 0.1801410f,  0.1801410f);
    const ull A7 = pk2(-0.0851330f, -0.0851330f);
    const ull A9 = pk2( 0.0208351f,  0.0208351f);

    float dl, dh; up2(dl, dh, dd);
    float al = fabsf(dl) * 1.5707964f;
    float ah = fabsf(dh) * 1.5707964f;
    float rl = __fdividef(1.0f, al);
    float rh = __fdividef(1.0f, ah);
    ull tk  = pk2(fminf(al, rl), fminf(ah, rh));
    ull tt2 = mul2(tk, tk);
    ull tt4 = mul2(tt2, tt2);
    ull e0  = fma2(tt2, A3, A1);
    ull e1  = fma2(tt2, A7, A5);
    e1 = fma2(tt4, A9, e1);
    ull pp = fma2(tt4, e1, e0);
    ull rr = mul2(tk, pp);
    float prl, prh; up2(prl, prh, rr);
    float aal = (al > 1.0f) ? (1.5707964f - prl) : prl;
    float aah = (ah > 1.0f) ? (1.5707964f - prh) : prh;
    aal = copysignf(aal, dl);
    aah = copysignf(aah, dh);
    return pk2(fmaf(aal, 0.15915494f, 0.25f),
               fmaf(aah, 0.15915494f, 0.25f));
}

__global__ __launch_bounds__(BLOCK, 7)
void lif_fused_kernel(const float* __restrict__ x,
                      const float* __restrict__ thr_p,
                      const float* __restrict__ cw,
                      const float* __restrict__ cb,
                      const float* __restrict__ sa,
                      float* __restrict__ out)
{
    const int p  = blockIdx.x * BLOCK + threadIdx.x;   // pair-lane id in [0, B*FH)
    const int fp = p & (FH - 1);
    const int b  = p >> 10;                            // FH = 2^10
    const int f  = fp * 2;

    const ull* __restrict__ xq = (const ull*)(x + (size_t)b * TT * FF + f);
    ull* __restrict__ oq       = (ull*)(out + (size_t)b * TT * FF + f);

    const float w0 = cw[0], w1 = cw[1], w2 = cw[2], w3 = cw[3], w4 = cw[4];
    const float bias = cb[0];
    const float thr0 = thr_p[0];
    const float satt = sa[0];

    // ---------- pass 1: sum x over t, REVERSED (t descending) ----------
    // The last-touched (early-t) lines stay freshest in L2 for pass 2.
    ull s0 = 0ull, s1 = 0ull, s2 = 0ull, s3 = 0ull;
    #pragma unroll 4
    for (int t = TT - 4; t >= 0; t -= 4) {
        s0 = add2(s0, xq[(t + 3) * FH]);
        s1 = add2(s1, xq[(t + 2) * FH]);
        s2 = add2(s2, xq[(t + 1) * FH]);
        s3 = add2(s3, xq[(t + 0) * FH]);
    }
    const ull sp_ = add2(add2(s0, s1), add2(s2, s3));
    float Sx, Sy; up2(Sx, Sy, sp_);

    const ull xe0p = xq[0];
    const ull xe1p = xq[FH];
    const ull xT2p = xq[(TT - 2) * FH];
    const ull xT1p = xq[(TT - 1) * FH];
    float e0l, e0h, e1l, e1h, t2l, t2h, t1l, t1h;
    up2(e0l, e0h, xe0p); up2(e1l, e1h, xe1p);
    up2(t2l, t2h, xT2p); up2(t1l, t1h, xT1p);

    // analytic sum of conv over t (linear conv, SAME zero padding)
    const float wsum = w0 + w1 + w2 + w3 + w4;
    const float cT = (float)TT * bias;
    float scx, scy;
    {
        float sc = cT + wsum * Sx - w0 * (t2l + t1l) - w1 * t1l
                 - w3 * e0l - w4 * (e0l + e1l);
        scx = 1.0f + 0.5f / (1.0f + expf(-satt * sc * (1.0f / (float)TT)));
    }
    {
        float sc = cT + wsum * Sy - w0 * (t2h + t1h) - w1 * t1h
                 - w3 * e0h - w4 * (e0h + e1h);
        scy = 1.0f + 0.5f / (1.0f + expf(-satt * sc * (1.0f / (float)TT)));
    }

    // ---------- packed constants ----------
    const ull W0 = pk2(w0, w0), W1 = pk2(w1, w1), W2 = pk2(w2, w2);
    const ull W3 = pk2(w3, w3), W4 = pk2(w4, w4);
    const ull SCp = pk2(scx, scy);
    const ull Bpp = pk2(bias * scx, bias * scy);
    const ull DEC = pk2(0.9f, 0.9f);
    const float k3f = 0.1f / 3.0f;
    const ull K3   = pk2(k3f, k3f);
    const ull TH0C = pk2(0.1f * thr0, 0.1f * thr0);

    // ---------- pass 2: fused conv + LIF with 8-deep register prefetch ----------
    ull m2v = 0ull, m1v = 0ull;
    ull c0v = xe0p, p1v = xe1p;

    ull Q[8];
    #pragma unroll
    for (int i = 0; i < 8; ++i) Q[i] = xq[(2 + i) * FH];   // x[t+2] for t=0..7

    ull memv = 0ull;
    ull thrv = pk2(thr0, thr0);
    ull h1v = 0ull, h2v = 0ull;

    // PFMODE: 1 = unconditional prefetch of x[T_+10]; 2 = guarded; 0 = none
    #define LIF_STEP(QI, T_, PFMODE)                                            \
    {                                                                            \
        ull p2v = Q[QI];                                                         \
        if ((PFMODE) == 1) {                                                     \
            Q[QI] = __ldcs(&xq[((T_) + 10) * FH]);                               \
        } else if ((PFMODE) == 2) {                                              \
            int idx_ = (T_) + 10;                                                \
            Q[QI] = (idx_ < TT) ? __ldcs(&xq[idx_ * FH]) : 0ull;                 \
        }                                                                        \
        ull cv = mul2(W0, m2v);                                                  \
        cv = fma2(W1, m1v, cv);                                                  \
        cv = fma2(W2, c0v, cv);                                                  \
        cv = fma2(W3, p1v, cv);                                                  \
        cv = fma2(W4, p2v, cv);                                                  \
        memv = fma2(DEC, memv, fma2(cv, SCp, Bpp));                              \
        /* thr pre-term computes in parallel with the atan chain */              \
        ull pre = fma2(DEC, thrv, fma2(K3, add2(h1v, h2v), TH0C));               \
        ull sp = atan_spike(sub2(memv, thrv));                                   \
        thrv = fma2(K3, sp, pre);                                                \
        memv = sub2(memv, mul2(sp, thrv));                                       \
        h1v = h2v; h2v = sp;                                                     \
        __stcs(&oq[(T_) * FH], sp);                                              \
        m2v = m1v; m1v = c0v; c0v = p1v; p1v = p2v;                              \
    }

    // chunks 0..13: t = 0..111, prefetch t+10 <= 121 always valid
    #pragma unroll 1
    for (int c = 0; c < 14; ++c) {
        const int tb = c * 8;
        LIF_STEP(0, tb + 0, 1)
        LIF_STEP(1, tb + 1, 1)
        LIF_STEP(2, tb + 2, 1)
        LIF_STEP(3, tb + 3, 1)
        LIF_STEP(4, tb + 4, 1)
        LIF_STEP(5, tb + 5, 1)
        LIF_STEP(6, tb + 6, 1)
        LIF_STEP(7, tb + 7, 1)
    }
    // chunk 14: t = 112..119, prefetch idx 122..129 guarded (>=128 -> 0)
    LIF_STEP(0, 112, 2)
    LIF_STEP(1, 113, 2)
    LIF_STEP(2, 114, 2)
    LIF_STEP(3, 115, 2)
    LIF_STEP(4, 116, 2)
    LIF_STEP(5, 117, 2)
    LIF_STEP(6, 118, 2)
    LIF_STEP(7, 119, 2)
    // chunk 15: t = 120..127, no prefetch; Q holds x[122..127], 0, 0
    LIF_STEP(0, 120, 0)
    LIF_STEP(1, 121, 0)
    LIF_STEP(2, 122, 0)
    LIF_STEP(3, 123, 0)
    LIF_STEP(4, 124, 0)
    LIF_STEP(5, 125, 0)
    LIF_STEP(6, 126, 0)
    LIF_STEP(7, 127, 0)

    #undef LIF_STEP

    // mem output appended after spikes
    ((ull*)(out + (size_t)BB * TT * FF))[p] = memv;
}

extern "C" void kernel_launch(void* const* d_in, const int* in_sizes, int n_in,
                              void* d_out, int out_size)
{
    const float* x    = (const float*)d_in[0];
    const float* thr0 = (const float*)d_in[1];
    const float* cw   = (const float*)d_in[2];
    const float* cb   = (const float*)d_in[3];
    const float* sa   = (const float*)d_in[4];
    float* out = (float*)d_out;

    const int pairs = BB * FH;                 // 131072 threads
    lif_fused_kernel<<<pairs / BLOCK, BLOCK>>>(x, thr0, cw, cb, sa, out);
}